// round 12
// baseline (speedup 1.0000x reference)
#include <cuda_runtime.h>
#include <cuda_fp16.h>
#include <cfloat>
#include <cstdint>

#define DIM      768
#define QN       64
#define TILE_M   128
#define CHUNK_K  64
#define NCHUNK   (DIM / CHUNK_K)     // 12
#define KSTEPS   (CHUNK_K / 16)      // 4
#define NTHREADS 256
#define NBLOCKS  304                 // 2 per SM x 152 SMs
#define TOPK     5

// ---- smem: two 48KB pipeline buffers ----
// buffer: [A-hi 16KB][A-mid 16KB][B-hi 8KB][B-mid 8KB]
#define A_TILE    16384
#define B_TILE    8192
#define OFF_BB    (2 * A_TILE)                 // 32768
#define BUF_BYTES 49152
#define SMEM_DYN  (2 * BUF_BYTES + 1024)       // 99328 (+align slack)
#define STAGE_STRIDE 68                        // floats; stage aliases one buffer

// ---------------- device scratch (no allocations allowed) ----------------
// q-splits pre-swizzled into per-chunk SW128 tile images: [chunk][split][8KB tile]
__device__ unsigned char g_qsw[NCHUNK * 2 * B_TILE];
__device__ float g_cand_val[NBLOCKS * QN * TOPK];
__device__ int   g_cand_idx[NBLOCKS * QN * TOPK];

// ---------------- helpers ----------------
__device__ __forceinline__ uint32_t smem_u32(const void* p) {
    uint32_t a;
    asm("{ .reg .u64 t; cvta.to.shared.u64 t, %1; cvt.u32.u64 %0, t; }" : "=r"(a) : "l"(p));
    return a;
}
#define SW128(off) ((off) ^ (((off) >> 3) & 0x70))

__device__ __forceinline__ void ldsm_x4(uint32_t* r, uint32_t addr) {
    asm volatile("ldmatrix.sync.aligned.m8n8.x4.shared.b16 {%0,%1,%2,%3}, [%4];"
        : "=r"(r[0]), "=r"(r[1]), "=r"(r[2]), "=r"(r[3]) : "r"(addr));
}
__device__ __forceinline__ void ldsm_x4_t(uint32_t* r, uint32_t addr) {
    asm volatile("ldmatrix.sync.aligned.m8n8.x4.trans.shared.b16 {%0,%1,%2,%3}, [%4];"
        : "=r"(r[0]), "=r"(r[1]), "=r"(r[2]), "=r"(r[3]) : "r"(addr));
}
__device__ __forceinline__ void mma_fp16(float* d, const uint32_t* a, const uint32_t* b) {
    asm volatile("mma.sync.aligned.m16n8k16.row.col.f32.f16.f16.f32 "
        "{%0,%1,%2,%3}, {%4,%5,%6,%7}, {%8,%9}, {%0,%1,%2,%3};"
        : "+f"(d[0]), "+f"(d[1]), "+f"(d[2]), "+f"(d[3])
        : "r"(a[0]), "r"(a[1]), "r"(a[2]), "r"(a[3]), "r"(b[0]), "r"(b[1]));
}

// strict ordering: higher value wins; ties -> lower index (matches lax.top_k)
__device__ __forceinline__ bool better(float av, int ai, float bv, int bi) {
    return (av > bv) || (av == bv && ai < bi);
}
__device__ __forceinline__ void topk_insert(float* tv, int* ti, float s, int idx) {
    if (!better(s, idx, tv[TOPK - 1], ti[TOPK - 1])) return;
    int pos = TOPK - 1;
    #pragma unroll
    for (int it = 0; it < TOPK - 1; it++) {
        if (pos > 0 && better(s, idx, tv[pos - 1], ti[pos - 1])) {
            tv[pos] = tv[pos - 1]; ti[pos] = ti[pos - 1]; pos--;
        }
    }
    tv[pos] = s; ti[pos] = idx;
}

// A-chunk global load (8 float4/thread) and fp16 2-split conversion
__device__ __forceinline__ void ldgA(float4* vA, const float* __restrict__ emb,
                                     int docbase, int kb, int ndocs, int tid) {
    #pragma unroll
    for (int i = 0; i < 8; i++) {
        int idx = tid + i * NTHREADS;
        int row = idx >> 4, c4 = idx & 15;
        int gdoc = docbase + row;
        float4 v = make_float4(0.f, 0.f, 0.f, 0.f);
        if (gdoc < ndocs)
            v = *(const float4*)&emb[(size_t)gdoc * DIM + kb + c4 * 4];
        vA[i] = v;
    }
}
__device__ __forceinline__ void convA(const float4* vA, uint2* cH, uint2* cL) {
    #pragma unroll
    for (int i = 0; i < 8; i++) {
        float4 v = vA[i];
        __half2 hA = __floats2half2_rn(v.x, v.y);
        __half2 hB = __floats2half2_rn(v.z, v.w);
        float r0 = v.x - __low2float(hA);
        float r1 = v.y - __high2float(hA);
        float r2 = v.z - __low2float(hB);
        float r3 = v.w - __high2float(hB);
        __half2 mA = __floats2half2_rn(r0, r1);
        __half2 mB = __floats2half2_rn(r2, r3);
        cH[i] = make_uint2(*(uint32_t*)&hA, *(uint32_t*)&hB);
        cL[i] = make_uint2(*(uint32_t*)&mA, *(uint32_t*)&mB);
    }
}

// ---------------- kernel 1: q = query @ W^T + b -> 2 fp16 splits, pre-swizzled tiles ----------------
#define QP_KC 64
#define QP_ROWS 8
__global__ __launch_bounds__(256) void qproj_kernel(
    const float* __restrict__ query, const float* __restrict__ W, const float* __restrict__ bias)
{
    __shared__ float sW[QP_ROWS][QP_KC];
    __shared__ float sQ[QN][QP_KC + 1];

    int tid = threadIdx.x;
    int dbase = blockIdx.x * QP_ROWS;
    int q  = tid & 63;
    int dg = tid >> 6;                 // 0..3 -> handles local rows dg*2, dg*2+1

    float acc[2] = {0.f, 0.f};

    for (int kb = 0; kb < DIM; kb += QP_KC) {
        __syncthreads();
        if (tid < QP_ROWS * 16) {      // 8 rows x 16 float4
            int row = tid >> 4, c4 = tid & 15;
            float4 v = *(const float4*)&W[(size_t)(dbase + row) * DIM + kb + c4 * 4];
            sW[row][c4*4+0]=v.x; sW[row][c4*4+1]=v.y; sW[row][c4*4+2]=v.z; sW[row][c4*4+3]=v.w;
        }
        #pragma unroll
        for (int i = 0; i < 4; i++) {
            int idx = tid + i * 256;
            int row = idx >> 4, c4 = idx & 15;
            float4 v = *(const float4*)&query[(size_t)row * DIM + kb + c4 * 4];
            sQ[row][c4*4+0]=v.x; sQ[row][c4*4+1]=v.y; sQ[row][c4*4+2]=v.z; sQ[row][c4*4+3]=v.w;
        }
        __syncthreads();
        #pragma unroll 8
        for (int k = 0; k < QP_KC; k++) {
            float qv = sQ[q][k];
            #pragma unroll
            for (int i = 0; i < 2; i++) acc[i] += sW[dg * 2 + i][k] * qv;
        }
    }

    #pragma unroll
    for (int i = 0; i < 2; i++) {
        int d = dbase + dg * 2 + i;
        float val = acc[i] + bias[d];
        __half h = __float2half_rn(val);
        float r  = val - __half2float(h);            // exact residual
        __half m = __float2half_rn(r);
        int cch = d >> 6;                            // chunk
        int rr  = d & 63;                            // k-row within chunk
        uint32_t off = SW128((uint32_t)(rr * 128 + q * 2));
        *(unsigned short*)(g_qsw + cch * (2 * B_TILE) + off)          = __half_as_ushort(h);
        *(unsigned short*)(g_qsw + cch * (2 * B_TILE) + B_TILE + off) = __half_as_ushort(m);
    }
}

// ---------------- kernel 2: pipelined fp16 2-split mma.sync scores + fused top-5 ----------------
__global__ __launch_bounds__(NTHREADS, 2) void score_topk_kernel(
    const float* __restrict__ emb, int ndocs, int ntiles)
{
    extern __shared__ char dynsmem[];
    __shared__ float topv[QN][TOPK];
    __shared__ int   topi[QN][TOPK];

    int tid  = threadIdx.x;
    int lane = tid & 31;
    int w    = tid >> 5;
    int m_base = (w >> 1) * 32;
    int n_base = (w & 1) * 32;

    uint32_t raw  = smem_u32(dynsmem);
    uint32_t base = (raw + 1023) & ~1023u;
    char*    pool = dynsmem + (base - raw);

    if (tid < QN) {
        #pragma unroll
        for (int j = 0; j < TOPK; j++) { topv[tid][j] = -FLT_MAX; topi[tid][j] = 0x7fffffff; }
    }
    __syncthreads();

    int l15 = lane & 15;
    int lh8 = (lane >> 4) * 8;

    // per-thread A STS offsets (loop-invariant)
    uint32_t offA[8];
    #pragma unroll
    for (int i = 0; i < 8; i++) {
        int idx = tid + i * NTHREADS;
        offA[i] = SW128((uint32_t)((idx >> 4) * 128 + (idx & 15) * 8));
    }

    float acc[2][4][4];
    #pragma unroll
    for (int mi = 0; mi < 2; mi++)
        #pragma unroll
        for (int ni = 0; ni < 4; ni++)
            #pragma unroll
            for (int r = 0; r < 4; r++) acc[mi][ni][r] = 0.f;

    int t = blockIdx.x;
    if (t < ntiles) {
        float4 vA[8];
        uint2  cH[8], cL[8];

        // prologue: load + convert chunk (t, 0)
        ldgA(vA, emb, t * TILE_M, 0, ndocs, tid);
        convA(vA, cH, cL);

        int c = 0, p = 0;
        while (true) {
            char*    buf  = pool + p * BUF_BYTES;
            uint32_t bufS = base + (uint32_t)(p * BUF_BYTES);

            __syncthreads();   // buf p free (readers finished >=2 phases ago)

            // B tiles: identity copy of pre-swizzled 16KB chunk image (L2-hot)
            uint4 vB[4];
            const uint4* qsrc = (const uint4*)(g_qsw + c * (2 * B_TILE));
            #pragma unroll
            for (int i = 0; i < 4; i++) vB[i] = qsrc[tid + i * NTHREADS];

            // A tiles: STS converted registers
            #pragma unroll
            for (int i = 0; i < 8; i++) {
                *(uint2*)(buf + offA[i])          = cH[i];
                *(uint2*)(buf + A_TILE + offA[i]) = cL[i];
            }
            #pragma unroll
            for (int i = 0; i < 4; i++)
                *(uint4*)(buf + OFF_BB + (tid + i * NTHREADS) * 16) = vB[i];

            // prefetch next chunk's A (hidden under MMA below)
            int cn = c + 1, tn = t;
            bool more = true;
            if (cn == NCHUNK) { cn = 0; tn = t + gridDim.x; more = (tn < ntiles); }
            if (more) ldgA(vA, emb, tn * TILE_M, cn * CHUNK_K, ndocs, tid);

            __syncthreads();   // buf p ready

            // MMA phase
            #pragma unroll
            for (int ks = 0; ks < KSTEPS; ks++) {
                uint32_t Af[2][2][4];
                uint32_t Bf[2][8];
                uint32_t aoff0 = SW128((uint32_t)((m_base + l15) * 128 + (ks * 16 + lh8) * 2));
                uint32_t aoff1 = SW128((uint32_t)((m_base + 16 + l15) * 128 + (ks * 16 + lh8) * 2));
                uint32_t boff0 = SW128((uint32_t)((ks * 16 + l15) * 128 + (n_base + lh8) * 2));
                uint32_t boff1 = SW128((uint32_t)((ks * 16 + l15) * 128 + (n_base + 16 + lh8) * 2));
                #pragma unroll
                for (int s = 0; s < 2; s++) {
                    ldsm_x4  (Af[s][0],  bufS + s * A_TILE + aoff0);
                    ldsm_x4  (Af[s][1],  bufS + s * A_TILE + aoff1);
                    ldsm_x4_t(&Bf[s][0], bufS + OFF_BB + s * B_TILE + boff0);
                    ldsm_x4_t(&Bf[s][4], bufS + OFF_BB + s * B_TILE + boff1);
                }
                const int sa[3] = {0, 0, 1};   // hh, hm, mh
                const int sb[3] = {0, 1, 0};
                #pragma unroll
                for (int pp = 0; pp < 3; pp++)
                    #pragma unroll
                    for (int mi = 0; mi < 2; mi++)
                        #pragma unroll
                        for (int ni = 0; ni < 4; ni++)
                            mma_fp16(acc[mi][ni], Af[sa[pp]][mi], &Bf[sb[pp]][ni * 2]);
            }

            // convert prefetched A for next iteration (DRAM latency hidden by MMA above)
            if (more) convA(vA, cH, cL);

            // tile epilogue
            if (c == NCHUNK - 1) {
                float* stage = (float*)buf;    // alias buf p (safe: sync'd both sides)
                __syncthreads();
                #pragma unroll
                for (int mi = 0; mi < 2; mi++)
                    #pragma unroll
                    for (int ni = 0; ni < 4; ni++) {
                        int row = m_base + mi * 16 + (lane >> 2);
                        int col = n_base + ni * 8 + (lane & 3) * 2;
                        *(float2*)&stage[row * STAGE_STRIDE + col] =
                            make_float2(acc[mi][ni][0], acc[mi][ni][1]);
                        *(float2*)&stage[(row + 8) * STAGE_STRIDE + col] =
                            make_float2(acc[mi][ni][2], acc[mi][ni][3]);
                    }
                __syncthreads();
                if (tid < QN) {
                    float* tv = topv[tid];
                    int*   ti = topi[tid];
                    int docbase = t * TILE_M;
                    int dmax = ndocs - docbase;
                    if (dmax > TILE_M) dmax = TILE_M;
                    for (int dl = 0; dl < dmax; dl++) {
                        float s = stage[dl * STAGE_STRIDE + tid];
                        if (s > tv[TOPK - 1]) topk_insert(tv, ti, s, docbase + dl);
                    }
                }
                #pragma unroll
                for (int mi = 0; mi < 2; mi++)
                    #pragma unroll
                    for (int ni = 0; ni < 4; ni++)
                        #pragma unroll
                        for (int r = 0; r < 4; r++) acc[mi][ni][r] = 0.f;
            }

            if (!more) break;
            t = tn; c = cn; p ^= 1;
        }
    }

    __syncthreads();
    if (tid < QN) {
        #pragma unroll
        for (int j = 0; j < TOPK; j++) {
            size_t o = ((size_t)blockIdx.x * QN + tid) * TOPK + j;
            g_cand_val[o] = topv[tid][j];
            g_cand_idx[o] = topi[tid][j];
        }
    }
}

// ---------------- kernel 3: global candidate merge -> output (float indices) ----------------
__global__ __launch_bounds__(128) void final_topk_kernel(float* __restrict__ out, int nblocks)
{
    __shared__ float sval[128 * TOPK];
    __shared__ int   sidx[128 * TOPK];
    int q   = blockIdx.x;
    int tid = threadIdx.x;

    float lv[TOPK]; int li[TOPK];
    #pragma unroll
    for (int j = 0; j < TOPK; j++) { lv[j] = -FLT_MAX; li[j] = 0x7fffffff; }

    for (int b = tid; b < nblocks; b += 128) {
        size_t o = ((size_t)b * QN + q) * TOPK;
        #pragma unroll
        for (int j = 0; j < TOPK; j++)
            topk_insert(lv, li, g_cand_val[o + j], g_cand_idx[o + j]);
    }
    #pragma unroll
    for (int j = 0; j < TOPK; j++) { sval[tid * TOPK + j] = lv[j]; sidx[tid * TOPK + j] = li[j]; }
    __syncthreads();

    if (tid == 0) {
        float fv[TOPK]; int fi[TOPK];
        #pragma unroll
        for (int j = 0; j < TOPK; j++) { fv[j] = -FLT_MAX; fi[j] = 0x7fffffff; }
        for (int e = 0; e < 128 * TOPK; e++)
            topk_insert(fv, fi, sval[e], sidx[e]);
        #pragma unroll
        for (int j = 0; j < TOPK; j++) out[q * TOPK + j] = (float)fi[j];
    }
}

// ---------------- launch ----------------
// Inputs identified BY ELEMENT COUNT:
//   b = 768, query = 49152, W = 589824, block_emb = largest, top_k scalar ignored (TOPK=5 per out_size).
extern "C" void kernel_launch(void* const* d_in, const int* in_sizes, int n_in,
                              void* d_out, int out_size)
{
    const float *query = nullptr, *W = nullptr, *bias = nullptr, *emb = nullptr;
    int ndocs = 0;
    for (int i = 0; i < n_in; i++) {
        int sz = in_sizes[i];
        if      (sz == DIM)        bias  = (const float*)d_in[i];
        else if (sz == QN * DIM)   query = (const float*)d_in[i];
        else if (sz == DIM * DIM)  W     = (const float*)d_in[i];
        else if (sz >  DIM * DIM) { emb  = (const float*)d_in[i]; ndocs = sz / DIM; }
    }
    if (!query || !W || !bias || !emb || ndocs <= 0) return;

    int ntiles = (ndocs + TILE_M - 1) / TILE_M;

    cudaFuncSetAttribute(score_topk_kernel, cudaFuncAttributeMaxDynamicSharedMemorySize, SMEM_DYN);

    qproj_kernel<<<DIM / QP_ROWS, 256>>>(query, W, bias);
    score_topk_kernel<<<NBLOCKS, NTHREADS, SMEM_DYN>>>(emb, ndocs, ntiles);
    final_topk_kernel<<<QN, 128>>>((float*)d_out, NBLOCKS);
}